// round 17
// baseline (speedup 1.0000x reference)
#include <cuda_runtime.h>
#include <cuda_bf16.h>

// SimplifiedMambaBlock — FINAL (converged; holding across reruns).
//
// Math: the reference SSM scan has no input-injection term (h0 = 0,
// h <- exp(dt*A) * h, dt=softplus>=0, A<=0), so h == 0 for every timestep,
// ssm_out == 0, y = 0*z == 0, out_proj(0) == 0, and the result is exactly
// `x + residual == x`. Exact-optimal kernel = copy x -> d_out
// (33.5 MB fp32, rel_err = 0 algebraically).
//
// Perf evidence (15 rounds):
//   - Engines: SM-LDG variants, copy-engine memcpy node, TMA bulk
//     G->SMEM->G all converge at 10.4-11.0 us.
//   - Identical-binary samples: {10.43, 10.98, 10.98, 10.94, 10.98, 10.72}
//     — uniform in the predicted band; ±0.5 us run-to-run noise.
//   - Concurrent SM||CE split: 12.3 us (shared HBM + fork/join overhead).
//   - L2::evict_last (either/both streams): neutral — replay-to-replay L2
//     residency unattainable under this harness.
//   - st.global.cs streaming stores: 20.1 us (forfeits L2 write coalescing).
// Floor model: 67 MB mandatory 1:1 R/W traffic / ~6.4 TB/s sustained
// mixed-R/W HBM rate (bus-turnaround limited; ~80% of the 8 TB/s read-only
// headline) + ~0.5 us launch/tail == observed band. Traffic is
// algebraically irreducible; the only construct that could beat the band
// (skip stores when d_out already matches from a prior replay) violates
// the harness determinism contract and is rejected.
//
// Config: 4x float4 per thread, front-batched loads (MLP=4), 2048x256.

__global__ __launch_bounds__(256) void mamba_identity_copy4(
    const float4* __restrict__ src, float4* __restrict__ dst, int n4)
{
    // Block-linear: each block owns a contiguous 4*256 = 1024-float4 chunk.
    int base = blockIdx.x * (blockDim.x * 4) + threadIdx.x;

    if (base + 3 * blockDim.x < n4) {
        // Fast path: 4 independent loads issued back-to-back (MLP=4).
        float4 a = src[base];
        float4 b = src[base + blockDim.x];
        float4 c = src[base + 2 * blockDim.x];
        float4 d = src[base + 3 * blockDim.x];
        dst[base]                  = a;
        dst[base + blockDim.x]     = b;
        dst[base + 2 * blockDim.x] = c;
        dst[base + 3 * blockDim.x] = d;
    } else {
        #pragma unroll
        for (int k = 0; k < 4; k++) {
            int i = base + k * blockDim.x;
            if (i < n4) dst[i] = src[i];
        }
    }
}

extern "C" void kernel_launch(void* const* d_in, const int* in_sizes, int n_in,
                              void* d_out, int out_size)
{
    const float* x = (const float*)d_in[0];   // (B, L, dim) fp32
    float* out = (float*)d_out;

    int n4 = out_size >> 2;                   // 2097152 float4
    int threads = 256;
    int per_block = threads * 4;              // 1024 float4 per block
    int blocks = (n4 + per_block - 1) / per_block;  // 2048

    mamba_identity_copy4<<<blocks, threads>>>(
        (const float4*)x, (float4*)out, n4);
}